// round 9
// baseline (speedup 1.0000x reference)
#include <cuda_runtime.h>
#include <math.h>

#define HIDDEN 128
#define MIX 8
#define MAXN 10000
#define MAXE 512000
#define FULLM 0xffffffffu

// Scratch (allocation-free rule: __device__ globals)
__device__ __align__(16) float g_T[MAXN * MIX];      // per-node hyper weights
__device__ int g_count[MAXN];
__device__ int g_cursor[MAXN];
__device__ int g_offsets[MAXN + 1];
__device__ __align__(8) int2 g_se[MAXE];             // sorted (src, edge_id)
__device__ int g_is64;

__device__ __forceinline__ float gelu_exact(float x) {
    return 0.5f * x * (1.0f + erff(x * 0.70710678118654752f));
}

__device__ __forceinline__ void load_edge(const void* ei, int e, int E, int& s, int& d) {
    if (g_is64) {
        const long long* p = (const long long*)ei;
        s = (int)p[e];
        d = (int)p[(size_t)E + e];
    } else {
        const int* p = (const int*)ei;
        s = p[e];
        d = p[(size_t)E + e];
    }
}

// Zero counters + detect int64-vs-int32 edge_index (node ids < N => int64 high words 0)
__global__ void prep_kernel(const unsigned int* __restrict__ w, int N) {
    int i = blockIdx.x * blockDim.x + threadIdx.x;
    if (i < N) { g_count[i] = 0; g_cursor[i] = 0; }
    if (i == 0) {
        int is64 = 1;
        #pragma unroll
        for (int k = 0; k < 64; k++)
            if (w[2 * k + 1] != 0u) is64 = 0;
        g_is64 = is64;
    }
}

__global__ void hist_kernel(const void* __restrict__ ei, int E) {
    int e = blockIdx.x * blockDim.x + threadIdx.x;
    if (e >= E) return;
    int s, d;
    load_edge(ei, e, E, s, d);
    atomicAdd(&g_count[d], 1);
}

#define SCAN_T 1024
__global__ void scan_kernel(int N) {
    __shared__ int wsum[32];
    int t = threadIdx.x;
    int lane = t & 31, wid = t >> 5;
    int per = (N + SCAN_T - 1) / SCAN_T;
    int beg = t * per;
    int end = min(beg + per, N);

    int local = 0;
    for (int i = beg; i < end; i++) local += g_count[i];

    int v = local;
    #pragma unroll
    for (int off = 1; off < 32; off <<= 1) {
        int u = __shfl_up_sync(FULLM, v, off);
        if (lane >= off) v += u;
    }
    if (lane == 31) wsum[wid] = v;
    __syncthreads();
    if (wid == 0) {
        int wv = wsum[lane];
        #pragma unroll
        for (int off = 1; off < 32; off <<= 1) {
            int u = __shfl_up_sync(FULLM, wv, off);
            if (lane >= off) wv += u;
        }
        wsum[lane] = wv;
    }
    __syncthreads();

    int warp_excl = (wid == 0) ? 0 : wsum[wid - 1];
    int run = warp_excl + (v - local);   // exclusive prefix for this thread
    for (int i = beg; i < end; i++) { g_offsets[i] = run; run += g_count[i]; }
    if (t == SCAN_T - 1) g_offsets[N] = run;
}

__global__ void reorder_kernel(const void* __restrict__ ei, int E) {
    int e = blockIdx.x * blockDim.x + threadIdx.x;
    if (e >= E) return;
    int s, d;
    load_edge(ei, e, E, s, d);
    int pos = g_offsets[d] + atomicAdd(&g_cursor[d], 1);
    g_se[pos] = make_int2(s, e);
}

// T[n,m] = dot( gelu( X[n,:] @ W_A^T ), W_B[m,:] )
__global__ void compute_T_kernel(const float* __restrict__ X,
                                 const float* __restrict__ WA,
                                 const float* __restrict__ WB,
                                 int N) {
    __shared__ float xs[16][HIDDEN];
    __shared__ float gs[16][HIDDEN];
    int t = threadIdx.x;
    int base = blockIdx.x * 16;

    #pragma unroll
    for (int r = 0; r < 16; r++) {
        int n = base + r;
        xs[r][t] = (n < N) ? X[(size_t)n * HIDDEN + t] : 0.f;
    }
    __syncthreads();

    const float* wa = WA + (size_t)t * HIDDEN;
    float acc[16];
    #pragma unroll
    for (int r = 0; r < 16; r++) acc[r] = 0.f;
    for (int k = 0; k < HIDDEN; k++) {
        float w = __ldg(wa + k);
        #pragma unroll
        for (int r = 0; r < 16; r++) acc[r] += xs[r][k] * w;
    }
    #pragma unroll
    for (int r = 0; r < 16; r++) gs[r][t] = gelu_exact(acc[r]);
    __syncthreads();

    int r = t >> 3, m = t & 7;
    int n = base + r;
    if (n < N) {
        const float* wb = WB + (size_t)m * HIDDEN;
        float a = 0.f;
        for (int k = 0; k < HIDDEN; k++) a += gs[r][k] * __ldg(wb + k);
        g_T[(size_t)n * MIX + m] = a;
    }
}

// ONE WARP per dst node. Lane l owns h = 4l..4l+3, all 8 mix accs in regs.
// WARP-COOPERATIVE EDGE FETCH: 32 edges' (src,eid) load in ONE coalesced LDG,
// broadcast via shfl -> no per-edge dependent index load. X/T prefetch depth-2
// with register-derivable addresses -> memory latency fully hidden under FMAs.
#define WPB 4
__global__ void __launch_bounds__(32 * WPB, 4)
fused_kernel(const float* __restrict__ X, float* __restrict__ out, int N) {
    int d = blockIdx.x * WPB + (threadIdx.x >> 5);
    if (d >= N) return;
    int lane = threadIdx.x & 31;

    int beg = g_offsets[d];
    int end = g_offsets[d + 1];
    if (beg == end) return;

    float a0[8], a1[8], a2[8], a3[8];
    #pragma unroll
    for (int m = 0; m < 8; m++) { a0[m] = 0.f; a1[m] = 0.f; a2[m] = 0.f; a3[m] = 0.f; }

    // ---- Phase A: agg[d, 4l..4l+3, m] += X[s, 4l..4l+3] * T[s, m] ----
    for (int base = beg; base < end; base += 32) {
        int nn = min(32, end - base);
        int sv = __ldg(&g_se[base + min(lane, nn - 1)].x);   // 1 coalesced load / 32 edges

        float4 xb[2], t0b[2], t1b[2];
        #pragma unroll
        for (int k = 0; k < 2; k++) {
            if (k < nn) {
                int s = __shfl_sync(FULLM, sv, k);
                xb[k] = __ldg((const float4*)(X + (size_t)s * HIDDEN) + lane);
                const float4* Tp = (const float4*)(g_T + (size_t)s * MIX);
                t0b[k] = __ldg(Tp);
                t1b[k] = __ldg(Tp + 1);
            }
        }
        for (int j = 0; j < nn; j++) {
            int sl = j & 1;
            float4 x = xb[sl], ta = t0b[sl], tb = t1b[sl];
            int jn = j + 2;
            if (jn < nn) {                                   // depth-2 prefetch
                int s = __shfl_sync(FULLM, sv, jn);
                xb[sl] = __ldg((const float4*)(X + (size_t)s * HIDDEN) + lane);
                const float4* Tp = (const float4*)(g_T + (size_t)s * MIX);
                t0b[sl] = __ldg(Tp);
                t1b[sl] = __ldg(Tp + 1);
            }
            float t[8] = {ta.x, ta.y, ta.z, ta.w, tb.x, tb.y, tb.z, tb.w};
            #pragma unroll
            for (int m = 0; m < 8; m++) {
                a0[m] = fmaf(x.x, t[m], a0[m]);
                a1[m] = fmaf(x.y, t[m], a1[m]);
                a2[m] = fmaf(x.z, t[m], a2[m]);
                a3[m] = fmaf(x.w, t[m], a3[m]);
            }
        }
    }

    // ---- Phase B: gelu in registers ----
    #pragma unroll
    for (int m = 0; m < 8; m++) {
        a0[m] = gelu_exact(a0[m]);
        a1[m] = gelu_exact(a1[m]);
        a2[m] = gelu_exact(a2[m]);
        a3[m] = gelu_exact(a3[m]);
    }

    // ---- Phase C: out[e, 4l..4l+3] = sum_m agg * T[s_e, m] ----
    for (int base = beg; base < end; base += 32) {
        int nn = min(32, end - base);
        int2 pv = __ldg(&g_se[base + min(lane, nn - 1)]);    // 1 coalesced load / 32 edges
        int sv = pv.x, ev = pv.y;

        float4 t0b[2], t1b[2];
        #pragma unroll
        for (int k = 0; k < 2; k++) {
            if (k < nn) {
                int s = __shfl_sync(FULLM, sv, k);
                const float4* Tp = (const float4*)(g_T + (size_t)s * MIX);
                t0b[k] = __ldg(Tp);
                t1b[k] = __ldg(Tp + 1);
            }
        }
        for (int j = 0; j < nn; j++) {
            int sl = j & 1;
            float4 ta = t0b[sl], tb = t1b[sl];
            int jn = j + 2;
            if (jn < nn) {
                int s = __shfl_sync(FULLM, sv, jn);
                const float4* Tp = (const float4*)(g_T + (size_t)s * MIX);
                t0b[sl] = __ldg(Tp);
                t1b[sl] = __ldg(Tp + 1);
            }
            float t[8] = {ta.x, ta.y, ta.z, ta.w, tb.x, tb.y, tb.z, tb.w};
            float4 r = make_float4(0.f, 0.f, 0.f, 0.f);
            #pragma unroll
            for (int m = 0; m < 8; m++) {
                r.x = fmaf(a0[m], t[m], r.x);
                r.y = fmaf(a1[m], t[m], r.y);
                r.z = fmaf(a2[m], t[m], r.z);
                r.w = fmaf(a3[m], t[m], r.w);
            }
            int e = __shfl_sync(FULLM, ev, j);
            *(float4*)(out + (size_t)e * HIDDEN + 4 * lane) = r;
        }
    }
}

// Optional tail: src/dst appended as floats (full-tuple output case)
__global__ void tail_kernel(const void* __restrict__ ei, float* __restrict__ out, int E) {
    int e = blockIdx.x * blockDim.x + threadIdx.x;
    if (e >= E) return;
    int s, d;
    load_edge(ei, e, E, s, d);
    out[(size_t)E * HIDDEN + e] = (float)s;
    out[(size_t)E * HIDDEN + E + e] = (float)d;
}

extern "C" void kernel_launch(void* const* d_in, const int* in_sizes, int n_in,
                              void* d_out, int out_size) {
    const float* X  = (const float*)d_in[0];
    const float* WA = (const float*)d_in[1];
    const float* WB = (const float*)d_in[2];
    const void*  ei = d_in[3];

    int N = in_sizes[0] / HIDDEN;   // 10000
    int E = in_sizes[3] / 2;        // 320000
    float* out = (float*)d_out;

    // Host-side stream/event handles (created once; host objects only, no device mem).
    static cudaStream_t s_side = nullptr;
    static cudaEvent_t ev_fork = nullptr, ev_T = nullptr, ev_r = nullptr, ev_join = nullptr;
    if (s_side == nullptr) {
        cudaStreamCreateWithFlags(&s_side, cudaStreamNonBlocking);
        cudaEventCreateWithFlags(&ev_fork, cudaEventDisableTiming);
        cudaEventCreateWithFlags(&ev_T, cudaEventDisableTiming);
        cudaEventCreateWithFlags(&ev_r, cudaEventDisableTiming);
        cudaEventCreateWithFlags(&ev_join, cudaEventDisableTiming);
    }

    bool want_tail = ((long long)out_size >= (long long)E * (HIDDEN + 2));

    // Main stream (0): prep -> hist -> scan -> reorder -> [wait T] -> fused -> [join]
    // Side stream:     [wait fork] compute_T -> (ev_T) ... [wait reorder] tail -> (ev_join)
    prep_kernel<<<(N + 255) / 256, 256>>>((const unsigned int*)ei, N);
    cudaEventRecord(ev_fork, 0);
    cudaStreamWaitEvent(s_side, ev_fork, 0);

    compute_T_kernel<<<(N + 15) / 16, 128, 0, s_side>>>(X, WA, WB, N);
    cudaEventRecord(ev_T, s_side);

    hist_kernel<<<(E + 255) / 256, 256>>>(ei, E);
    scan_kernel<<<1, SCAN_T>>>(N);
    reorder_kernel<<<(E + 255) / 256, 256>>>(ei, E);
    cudaEventRecord(ev_r, 0);

    cudaStreamWaitEvent(0, ev_T, 0);
    fused_kernel<<<(N + WPB - 1) / WPB, 32 * WPB>>>(X, out, N);

    if (want_tail) {
        cudaStreamWaitEvent(s_side, ev_r, 0);
        tail_kernel<<<(E + 255) / 256, 256, 0, s_side>>>(ei, out, E);
        cudaEventRecord(ev_join, s_side);
        cudaStreamWaitEvent(0, ev_join, 0);
    }
}

// round 10
// speedup vs baseline: 1.1780x; 1.1780x over previous
#include <cuda_runtime.h>
#include <math.h>

#define HIDDEN 128
#define MIX 8
#define MAXN 10000
#define MAXE 512000
#define FULLM 0xffffffffu

// Scratch (allocation-free rule: __device__ globals)
__device__ __align__(16) float g_T[MAXN * MIX];      // per-node hyper weights
__device__ int g_count[MAXN];
__device__ int g_cursor[MAXN];
__device__ int g_offsets[MAXN + 1];
__device__ __align__(8) int2 g_se[MAXE];             // sorted (src, edge_id)
__device__ int g_is64;

__device__ __forceinline__ float gelu_exact(float x) {
    return 0.5f * x * (1.0f + erff(x * 0.70710678118654752f));
}

__device__ __forceinline__ void load_edge(const void* ei, int e, int E, int& s, int& d) {
    if (g_is64) {
        const long long* p = (const long long*)ei;
        s = (int)p[e];
        d = (int)p[(size_t)E + e];
    } else {
        const int* p = (const int*)ei;
        s = p[e];
        d = p[(size_t)E + e];
    }
}

// Zero counters + detect int64-vs-int32 edge_index (node ids < N => int64 high words 0)
__global__ void prep_kernel(const unsigned int* __restrict__ w, int N) {
    int i = blockIdx.x * blockDim.x + threadIdx.x;
    if (i < N) { g_count[i] = 0; g_cursor[i] = 0; }
    if (i == 0) {
        int is64 = 1;
        #pragma unroll
        for (int k = 0; k < 64; k++)
            if (w[2 * k + 1] != 0u) is64 = 0;
        g_is64 = is64;
    }
}

__global__ void hist_kernel(const void* __restrict__ ei, int E) {
    int e = blockIdx.x * blockDim.x + threadIdx.x;
    if (e >= E) return;
    int s, d;
    load_edge(ei, e, E, s, d);
    atomicAdd(&g_count[d], 1);
}

#define SCAN_T 1024
__global__ void scan_kernel(int N) {
    __shared__ int wsum[32];
    int t = threadIdx.x;
    int lane = t & 31, wid = t >> 5;
    int per = (N + SCAN_T - 1) / SCAN_T;
    int beg = t * per;
    int end = min(beg + per, N);

    int local = 0;
    for (int i = beg; i < end; i++) local += g_count[i];

    int v = local;
    #pragma unroll
    for (int off = 1; off < 32; off <<= 1) {
        int u = __shfl_up_sync(FULLM, v, off);
        if (lane >= off) v += u;
    }
    if (lane == 31) wsum[wid] = v;
    __syncthreads();
    if (wid == 0) {
        int wv = wsum[lane];
        #pragma unroll
        for (int off = 1; off < 32; off <<= 1) {
            int u = __shfl_up_sync(FULLM, wv, off);
            if (lane >= off) wv += u;
        }
        wsum[lane] = wv;
    }
    __syncthreads();

    int warp_excl = (wid == 0) ? 0 : wsum[wid - 1];
    int run = warp_excl + (v - local);   // exclusive prefix for this thread
    for (int i = beg; i < end; i++) { g_offsets[i] = run; run += g_count[i]; }
    if (t == SCAN_T - 1) g_offsets[N] = run;
}

__global__ void reorder_kernel(const void* __restrict__ ei, int E) {
    int e = blockIdx.x * blockDim.x + threadIdx.x;
    if (e >= E) return;
    int s, d;
    load_edge(ei, e, E, s, d);
    int pos = g_offsets[d] + atomicAdd(&g_cursor[d], 1);
    g_se[pos] = make_int2(s, e);
}

// T[n,m] = dot( gelu( X[n,:] @ W_A^T ), W_B[m,:] )
__global__ void compute_T_kernel(const float* __restrict__ X,
                                 const float* __restrict__ WA,
                                 const float* __restrict__ WB,
                                 int N) {
    __shared__ float xs[16][HIDDEN];
    __shared__ float gs[16][HIDDEN];
    int t = threadIdx.x;
    int base = blockIdx.x * 16;

    #pragma unroll
    for (int r = 0; r < 16; r++) {
        int n = base + r;
        xs[r][t] = (n < N) ? X[(size_t)n * HIDDEN + t] : 0.f;
    }
    __syncthreads();

    const float* wa = WA + (size_t)t * HIDDEN;
    float acc[16];
    #pragma unroll
    for (int r = 0; r < 16; r++) acc[r] = 0.f;
    for (int k = 0; k < HIDDEN; k++) {
        float w = __ldg(wa + k);
        #pragma unroll
        for (int r = 0; r < 16; r++) acc[r] += xs[r][k] * w;
    }
    #pragma unroll
    for (int r = 0; r < 16; r++) gs[r][t] = gelu_exact(acc[r]);
    __syncthreads();

    int r = t >> 3, m = t & 7;
    int n = base + r;
    if (n < N) {
        const float* wb = WB + (size_t)m * HIDDEN;
        float a = 0.f;
        for (int k = 0; k < HIDDEN; k++) a += gs[r][k] * __ldg(wb + k);
        g_T[(size_t)n * MIX + m] = a;
    }
}

// TWO WARPS per dst node (h-halves of 64). Lane owns an h-PAIR (float2) in its
// half, plus all 8 mix accumulators -> only 16 accumulator regs/thread.
// __launch_bounds__(256, 4) caps regs at 64 -> 32 warps/SM (8/SMSP), doubling
// the warps available to hide the ~240cyc L2 gather latency. Pipelined depth-1
// (R8 structure, the measured best; no dynamic-indexed register arrays).
#define DPB 4   // dsts per 256-thread block (2 warps each)
__global__ void __launch_bounds__(64 * DPB, 4)
fused_kernel(const float* __restrict__ X, float* __restrict__ out, int N) {
    int pair = threadIdx.x >> 6;                 // 0..DPB-1
    int d = blockIdx.x * DPB + pair;
    if (d >= N) return;
    int half = (threadIdx.x >> 5) & 1;           // which h-half (0: h<64, 1: h>=64)
    int lane = threadIdx.x & 31;
    int hoff = half * 32 + lane;                 // float2 index into the 128-wide row

    int beg = g_offsets[d];
    int end = g_offsets[d + 1];
    if (beg == end) return;

    float aLo[8], aHi[8];                        // acc for h = 2*hoff, 2*hoff+1
    #pragma unroll
    for (int m = 0; m < 8; m++) { aLo[m] = 0.f; aHi[m] = 0.f; }

    // ---- Phase A (pipelined): agg += X[s, h-pair] * T[s, m] ----
    {
        int sc = __ldg(&g_se[beg].x);
        float2 xc = __ldg((const float2*)(X + (size_t)sc * HIDDEN) + hoff);
        const float4* Tc = (const float4*)(g_T + (size_t)sc * MIX);
        float4 tc0 = __ldg(Tc), tc1 = __ldg(Tc + 1);

        for (int i = beg; i < end - 1; i++) {
            int sn = __ldg(&g_se[i + 1].x);
            float2 xn = __ldg((const float2*)(X + (size_t)sn * HIDDEN) + hoff);
            const float4* Tn = (const float4*)(g_T + (size_t)sn * MIX);
            float4 tn0 = __ldg(Tn), tn1 = __ldg(Tn + 1);

            float t[8] = {tc0.x, tc0.y, tc0.z, tc0.w, tc1.x, tc1.y, tc1.z, tc1.w};
            #pragma unroll
            for (int m = 0; m < 8; m++) {
                aLo[m] = fmaf(xc.x, t[m], aLo[m]);
                aHi[m] = fmaf(xc.y, t[m], aHi[m]);
            }
            xc = xn; tc0 = tn0; tc1 = tn1;
        }
        float t[8] = {tc0.x, tc0.y, tc0.z, tc0.w, tc1.x, tc1.y, tc1.z, tc1.w};
        #pragma unroll
        for (int m = 0; m < 8; m++) {
            aLo[m] = fmaf(xc.x, t[m], aLo[m]);
            aHi[m] = fmaf(xc.y, t[m], aHi[m]);
        }
    }

    // ---- Phase B: gelu in registers ----
    #pragma unroll
    for (int m = 0; m < 8; m++) {
        aLo[m] = gelu_exact(aLo[m]);
        aHi[m] = gelu_exact(aHi[m]);
    }

    // ---- Phase C (pipelined): out[e, h-pair] = sum_m agg * T[s_e, m] ----
    {
        int2 pc = __ldg(&g_se[beg]);
        const float4* Tc = (const float4*)(g_T + (size_t)pc.x * MIX);
        float4 tc0 = __ldg(Tc), tc1 = __ldg(Tc + 1);

        for (int i = beg; i < end - 1; i++) {
            int2 pn = __ldg(&g_se[i + 1]);
            const float4* Tn = (const float4*)(g_T + (size_t)pn.x * MIX);
            float4 tn0 = __ldg(Tn), tn1 = __ldg(Tn + 1);

            float t[8] = {tc0.x, tc0.y, tc0.z, tc0.w, tc1.x, tc1.y, tc1.z, tc1.w};
            float2 r = make_float2(0.f, 0.f);
            #pragma unroll
            for (int m = 0; m < 8; m++) {
                r.x = fmaf(aLo[m], t[m], r.x);
                r.y = fmaf(aHi[m], t[m], r.y);
            }
            *((float2*)(out + (size_t)pc.y * HIDDEN) + hoff) = r;
            pc = pn; tc0 = tn0; tc1 = tn1;
        }
        float t[8] = {tc0.x, tc0.y, tc0.z, tc0.w, tc1.x, tc1.y, tc1.z, tc1.w};
        float2 r = make_float2(0.f, 0.f);
        #pragma unroll
        for (int m = 0; m < 8; m++) {
            r.x = fmaf(aLo[m], t[m], r.x);
            r.y = fmaf(aHi[m], t[m], r.y);
        }
        *((float2*)(out + (size_t)pc.y * HIDDEN) + hoff) = r;
    }
}

// Optional tail: src/dst appended as floats (full-tuple output case)
__global__ void tail_kernel(const void* __restrict__ ei, float* __restrict__ out, int E) {
    int e = blockIdx.x * blockDim.x + threadIdx.x;
    if (e >= E) return;
    int s, d;
    load_edge(ei, e, E, s, d);
    out[(size_t)E * HIDDEN + e] = (float)s;
    out[(size_t)E * HIDDEN + E + e] = (float)d;
}

extern "C" void kernel_launch(void* const* d_in, const int* in_sizes, int n_in,
                              void* d_out, int out_size) {
    const float* X  = (const float*)d_in[0];
    const float* WA = (const float*)d_in[1];
    const float* WB = (const float*)d_in[2];
    const void*  ei = d_in[3];

    int N = in_sizes[0] / HIDDEN;   // 10000
    int E = in_sizes[3] / 2;        // 320000
    float* out = (float*)d_out;

    // Host-side stream/event handles (created once; host objects only, no device mem).
    static cudaStream_t s_side = nullptr;
    static cudaEvent_t ev_fork = nullptr, ev_T = nullptr, ev_r = nullptr, ev_join = nullptr;
    if (s_side == nullptr) {
        cudaStreamCreateWithFlags(&s_side, cudaStreamNonBlocking);
        cudaEventCreateWithFlags(&ev_fork, cudaEventDisableTiming);
        cudaEventCreateWithFlags(&ev_T, cudaEventDisableTiming);
        cudaEventCreateWithFlags(&ev_r, cudaEventDisableTiming);
        cudaEventCreateWithFlags(&ev_join, cudaEventDisableTiming);
    }

    bool want_tail = ((long long)out_size >= (long long)E * (HIDDEN + 2));

    // Main stream (0): prep -> hist -> scan -> reorder -> [wait T] -> fused -> [join]
    // Side stream:     [wait fork] compute_T -> (ev_T) ... [wait reorder] tail -> (ev_join)
    prep_kernel<<<(N + 255) / 256, 256>>>((const unsigned int*)ei, N);
    cudaEventRecord(ev_fork, 0);
    cudaStreamWaitEvent(s_side, ev_fork, 0);

    compute_T_kernel<<<(N + 15) / 16, 128, 0, s_side>>>(X, WA, WB, N);
    cudaEventRecord(ev_T, s_side);

    hist_kernel<<<(E + 255) / 256, 256>>>(ei, E);
    scan_kernel<<<1, SCAN_T>>>(N);
    reorder_kernel<<<(E + 255) / 256, 256>>>(ei, E);
    cudaEventRecord(ev_r, 0);

    cudaStreamWaitEvent(0, ev_T, 0);
    fused_kernel<<<(N + DPB - 1) / DPB, 64 * DPB>>>(X, out, N);

    if (want_tail) {
        cudaStreamWaitEvent(s_side, ev_r, 0);
        tail_kernel<<<(E + 255) / 256, 256, 0, s_side>>>(ei, out, E);
        cudaEventRecord(ev_join, s_side);
        cudaStreamWaitEvent(0, ev_join, 0);
    }
}